// round 13
// baseline (speedup 1.0000x reference)
#include <cuda_runtime.h>
#include <cuda_bf16.h>
#include <cstdint>
#include <math.h>

#define B_ 2
#define S_ 2048
#define DIM_ 1024
#define H_ 16
#define HD_ 64
#define HALF_ 32
#define NQKV 3072

__device__ float g_qkv[B_ * S_ * NQKV];    // fused q|k|v (tf32-rounded, q pre-scaled)
__device__ float g_o[B_ * S_ * DIM_];

__device__ __forceinline__ unsigned f32_to_tf32(float x) {
    unsigned r;
    asm("cvt.rna.tf32.f32 %0, %1;" : "=r"(r) : "f"(x));
    return r;
}
__device__ __forceinline__ float round_tf32f(float x) {
    return __uint_as_float(f32_to_tf32(x));
}

__device__ __forceinline__ uint32_t smem_to_u32(const void* p) {
    uint32_t a;
    asm("{ .reg .u64 t; cvta.to.shared.u64 t, %1; cvt.u32.u64 %0, t; }"
        : "=r"(a) : "l"(p));
    return a;
}

#define CP_ASYNC16(dst_u32, src_ptr) \
    asm volatile("cp.async.cg.shared.global [%0], [%1], 16;" :: "r"(dst_u32), "l"(src_ptr))
#define CP_COMMIT() asm volatile("cp.async.commit_group;" ::: "memory")
#define CP_WAIT(n) asm volatile("cp.async.wait_group %0;" :: "n"(n) : "memory")

#define MMA_TF32(acc, a0, a1, a2, a3, b0, b1)                                  \
    asm volatile(                                                              \
        "mma.sync.aligned.m16n8k8.row.col.f32.tf32.tf32.f32 "                  \
        "{%0,%1,%2,%3}, {%4,%5,%6,%7}, {%8,%9}, {%0,%1,%2,%3};"                \
        : "+f"(acc[0]), "+f"(acc[1]), "+f"(acc[2]), "+f"(acc[3])               \
        : "r"(a0), "r"(a1), "r"(a2), "r"(a3), "r"(b0), "r"(b1))

// ---------------------------------------------------------------------------
// TF32 mma.sync GEMM, R3-proven config: LDG -> cvt.rna -> STS staging (no
// pre-pass needed), scalar fragment LDS. C[M,NS] = A @ W^T where W rows are
// selected from {W0,W1,W2} by output-column segment (handles stacked QKV
// weights from 3 separate input pointers).
// mode=1: RoPE on cols<2048, round outputs to tf32, pre-scale q by 0.125.
// ---------------------------------------------------------------------------
#define LDT 36

__global__ void __launch_bounds__(256) gemm_tf32(const float* __restrict__ A,
                                                 const float* __restrict__ W0,
                                                 const float* __restrict__ W1,
                                                 const float* __restrict__ W2,
                                                 float* __restrict__ C,
                                                 int NS, int K, int mode,
                                                 const float* __restrict__ cosb,
                                                 const float* __restrict__ sinb) {
    __shared__ unsigned As[128 * LDT];
    __shared__ unsigned Bs[128 * LDT];

    const int tid = threadIdx.x;
    const int wid = tid >> 5;
    const int lane = tid & 31;
    const int gid = lane >> 2;
    const int tig = lane & 3;
    const int warp_m = wid >> 2;
    const int warp_n = wid & 3;
    const int bx = blockIdx.x;
    const int by = blockIdx.y;

    const float* Ab = A + (size_t)(by * 128) * K;
    const int rowg = bx * 128;
    const int seg = rowg >> 10;
    const float* W = (seg == 0) ? W0 : (seg == 1) ? W1 : W2;
    const float* Bb = W + (size_t)(rowg & 1023) * K;

    float acc[4][4][4];
#pragma unroll
    for (int mi = 0; mi < 4; mi++)
#pragma unroll
        for (int ni = 0; ni < 4; ni++)
#pragma unroll
            for (int c = 0; c < 4; c++) acc[mi][ni][c] = 0.0f;

    for (int k0 = 0; k0 < K; k0 += 32) {
#pragma unroll
        for (int i = 0; i < 4; i++) {
            int idx = tid + i * 256;
            int row = idx >> 3;
            int c4 = idx & 7;
            float4 v = *(const float4*)(Ab + (size_t)row * K + k0 + c4 * 4);
            unsigned* dst = &As[row * LDT + c4 * 4];
            dst[0] = f32_to_tf32(v.x); dst[1] = f32_to_tf32(v.y);
            dst[2] = f32_to_tf32(v.z); dst[3] = f32_to_tf32(v.w);
        }
#pragma unroll
        for (int i = 0; i < 4; i++) {
            int idx = tid + i * 256;
            int row = idx >> 3;
            int c4 = idx & 7;
            float4 v = *(const float4*)(Bb + (size_t)row * K + k0 + c4 * 4);
            unsigned* dst = &Bs[row * LDT + c4 * 4];
            dst[0] = f32_to_tf32(v.x); dst[1] = f32_to_tf32(v.y);
            dst[2] = f32_to_tf32(v.z); dst[3] = f32_to_tf32(v.w);
        }
        __syncthreads();

#pragma unroll
        for (int ks = 0; ks < 32; ks += 8) {
            unsigned a[4][4], b[4][2];
#pragma unroll
            for (int mi = 0; mi < 4; mi++) {
                int r = warp_m * 64 + mi * 16 + gid;
                int cc = ks + tig;
                a[mi][0] = As[r * LDT + cc];
                a[mi][1] = As[(r + 8) * LDT + cc];
                a[mi][2] = As[r * LDT + cc + 4];
                a[mi][3] = As[(r + 8) * LDT + cc + 4];
            }
#pragma unroll
            for (int ni = 0; ni < 4; ni++) {
                int n = warp_n * 32 + ni * 8 + gid;
                int cc = ks + tig;
                b[ni][0] = Bs[n * LDT + cc];
                b[ni][1] = Bs[n * LDT + cc + 4];
            }
#pragma unroll
            for (int mi = 0; mi < 4; mi++)
#pragma unroll
                for (int ni = 0; ni < 4; ni++)
                    MMA_TF32(acc[mi][ni], a[mi][0], a[mi][1], a[mi][2], a[mi][3],
                             b[ni][0], b[ni][1]);
        }
        __syncthreads();
    }

#pragma unroll
    for (int mi = 0; mi < 4; mi++) {
#pragma unroll
        for (int ni = 0; ni < 4; ni++) {
            int rA = by * 128 + warp_m * 64 + mi * 16 + gid;
            int rB = rA + 8;
            int cc = bx * 128 + warp_n * 32 + ni * 8 + 2 * tig;
            float e0 = acc[mi][ni][0], o0 = acc[mi][ni][1];
            float e1 = acc[mi][ni][2], o1 = acc[mi][ni][3];
            if (mode) {
                if (cc < 2048) {
                    int p = (cc & 63) >> 1;
                    float cA = cosb[(rA & (S_ - 1)) * HALF_ + p];
                    float sA = sinb[(rA & (S_ - 1)) * HALF_ + p];
                    float cB = cosb[(rB & (S_ - 1)) * HALF_ + p];
                    float sB = sinb[(rB & (S_ - 1)) * HALF_ + p];
                    float t0 = e0 * cA - o0 * sA, t1 = e0 * sA + o0 * cA;
                    e0 = t0; o0 = t1;
                    float t2 = e1 * cB - o1 * sB, t3 = e1 * sB + o1 * cB;
                    e1 = t2; o1 = t3;
                }
                float sc = (cc < 1024) ? 0.125f : 1.0f;
                e0 = round_tf32f(e0 * sc); o0 = round_tf32f(o0 * sc);
                e1 = round_tf32f(e1 * sc); o1 = round_tf32f(o1 * sc);
            }
            *(float2*)(C + (size_t)rA * NS + cc) = make_float2(e0, o0);
            *(float2*)(C + (size_t)rB * NS + cc) = make_float2(e1, o1);
        }
    }
}

// ---------------------------------------------------------------------------
// Flash attention, tf32 mma, cp.async double-buffered K/V tiles.
// Work balancing: each CTA processes TWO complementary query blocks
// (qb and 15-qb), so every CTA does exactly 32 key-tile units and the
// 256-CTA grid fits one balanced wave (2 CTAs/SM x 148 SMs = 296 slots).
// ---------------------------------------------------------------------------
#define KLDT 68
#define VLDT 72
#define KTILE (64 * KLDT)
#define VTILE (64 * VLDT)
#define FL_SMEM ((2 * KTILE + 2 * VTILE) * 4)   // 70656 B

__global__ void __launch_bounds__(256, 2) flash_mma(const float* __restrict__ QKV,
                                                    float* __restrict__ O) {
    extern __shared__ float sm[];
    const uint32_t smem_base = smem_to_u32(sm);
    float* Kbuf[2] = {sm, sm + KTILE};
    float* Vbuf[2] = {sm + 2 * KTILE, sm + 2 * KTILE + VTILE};

    const int tid = threadIdx.x;
    const int wid = tid >> 5;
    const int lane = tid & 31;
    const int gid = lane >> 2;
    const int tig = lane & 3;
    const int bx = blockIdx.x;        // 0..7
    const int h = blockIdx.y;
    const int b = blockIdx.z;

    const int srcA = (lane & ~3) | (tig >> 1);
    const int srcB = srcA + 2;
    const int par = tig & 1;

    const int crow = tid >> 4;        // tile-copy row base
    const int cc4 = tid & 15;

    auto issue_tile = [&](int kt, int s) {
        uint32_t kb = smem_base + (uint32_t)(s * KTILE) * 4;
        uint32_t vb = smem_base + (uint32_t)(2 * KTILE + s * VTILE) * 4;
#pragma unroll
        for (int i = 0; i < 4; i++) {
            int row = crow + i * 16;
            size_t g = (size_t)(b * S_ + kt + row) * NQKV + h * HD_ + cc4 * 4;
            CP_ASYNC16(kb + (uint32_t)(row * KLDT + cc4 * 4) * 4, QKV + g + 1024);
            CP_ASYNC16(vb + (uint32_t)(row * VLDT + cc4 * 4) * 4, QKV + g + 2048);
        }
    };

#pragma unroll 1
    for (int pass = 0; pass < 2; pass++) {
        const int qb = pass ? bx : (15 - bx);   // heavy block first
        const int qbase = qb * 128;

        __syncthreads();   // prior pass's tile reads complete before Q staging

        // Stage Q tile into K region, pull fragments
#pragma unroll
        for (int i = 0; i < 8; i++) {
            int lin = tid + i * 256;
            int row = lin >> 4;
            int c4 = lin & 15;
            *(float4*)(&sm[row * KLDT + c4 * 4]) =
                *(const float4*)(QKV + (size_t)(b * S_ + qbase + row) * NQKV + h * HD_ + c4 * 4);
        }
        __syncthreads();

        const int r0 = wid * 16;
        unsigned qf[8][4];
#pragma unroll
        for (int ks = 0; ks < 8; ks++) {
            int c = ks * 8 + tig;
            qf[ks][0] = __float_as_uint(sm[(r0 + gid) * KLDT + c]);
            qf[ks][1] = __float_as_uint(sm[(r0 + gid + 8) * KLDT + c]);
            qf[ks][2] = __float_as_uint(sm[(r0 + gid) * KLDT + c + 4]);
            qf[ks][3] = __float_as_uint(sm[(r0 + gid + 8) * KLDT + c + 4]);
        }
        __syncthreads();   // Q reads done before cp.async overwrites K region

        float oacc[8][4];
#pragma unroll
        for (int nd = 0; nd < 8; nd++)
#pragma unroll
            for (int c = 0; c < 4; c++) oacc[nd][c] = 0.0f;
        float m0 = -1e30f, m1 = -1e30f, l0 = 0.0f, l1 = 0.0f;

        const int r0g = qbase + r0;
        const int kend = qbase + 128;

        issue_tile(0, 0);
        CP_COMMIT();

        int buf = 0;
#pragma unroll 1
        for (int kt = 0; kt < kend; kt += 64) {
            CP_WAIT(0);
            __syncthreads();
            if (kt + 64 < kend) {
                issue_tile(kt + 64, buf ^ 1);
                CP_COMMIT();
            }

            if (kt <= r0g + 15) {
                const float* Ks = Kbuf[buf];
                const float* Vs = Vbuf[buf];

                float sf[8][4];
#pragma unroll
                for (int nt = 0; nt < 8; nt++) {
                    sf[nt][0] = 0.0f; sf[nt][1] = 0.0f;
                    sf[nt][2] = 0.0f; sf[nt][3] = 0.0f;
#pragma unroll
                    for (int ks = 0; ks < 8; ks++) {
                        unsigned b0 = __float_as_uint(Ks[(nt * 8 + gid) * KLDT + ks * 8 + tig]);
                        unsigned b1 = __float_as_uint(Ks[(nt * 8 + gid) * KLDT + ks * 8 + tig + 4]);
                        MMA_TF32(sf[nt], qf[ks][0], qf[ks][1], qf[ks][2], qf[ks][3], b0, b1);
                    }
                }

                if (kt + 63 > r0g) {
                    int rA = r0g + gid;
                    int rB = rA + 8;
#pragma unroll
                    for (int nt = 0; nt < 8; nt++) {
                        int colb = kt + nt * 8 + 2 * tig;
                        if (colb > rA) sf[nt][0] = -1e30f;
                        if (colb + 1 > rA) sf[nt][1] = -1e30f;
                        if (colb > rB) sf[nt][2] = -1e30f;
                        if (colb + 1 > rB) sf[nt][3] = -1e30f;
                    }
                }

                float mx0 = m0, mx1 = m1;
#pragma unroll
                for (int nt = 0; nt < 8; nt++) {
                    mx0 = fmaxf(mx0, fmaxf(sf[nt][0], sf[nt][1]));
                    mx1 = fmaxf(mx1, fmaxf(sf[nt][2], sf[nt][3]));
                }
                mx0 = fmaxf(mx0, __shfl_xor_sync(0xffffffffu, mx0, 1));
                mx0 = fmaxf(mx0, __shfl_xor_sync(0xffffffffu, mx0, 2));
                mx1 = fmaxf(mx1, __shfl_xor_sync(0xffffffffu, mx1, 1));
                mx1 = fmaxf(mx1, __shfl_xor_sync(0xffffffffu, mx1, 2));

                float corr0 = __expf(m0 - mx0);
                float corr1 = __expf(m1 - mx1);
                float rs0 = 0.0f, rs1 = 0.0f;
#pragma unroll
                for (int nt = 0; nt < 8; nt++) {
                    sf[nt][0] = __expf(sf[nt][0] - mx0);
                    sf[nt][1] = __expf(sf[nt][1] - mx0);
                    sf[nt][2] = __expf(sf[nt][2] - mx1);
                    sf[nt][3] = __expf(sf[nt][3] - mx1);
                    rs0 += sf[nt][0] + sf[nt][1];
                    rs1 += sf[nt][2] + sf[nt][3];
                }
                rs0 += __shfl_xor_sync(0xffffffffu, rs0, 1);
                rs0 += __shfl_xor_sync(0xffffffffu, rs0, 2);
                rs1 += __shfl_xor_sync(0xffffffffu, rs1, 1);
                rs1 += __shfl_xor_sync(0xffffffffu, rs1, 2);
                l0 = l0 * corr0 + rs0;
                l1 = l1 * corr1 + rs1;
                m0 = mx0; m1 = mx1;
#pragma unroll
                for (int nd = 0; nd < 8; nd++) {
                    oacc[nd][0] *= corr0; oacc[nd][1] *= corr0;
                    oacc[nd][2] *= corr1; oacc[nd][3] *= corr1;
                }

#pragma unroll
                for (int ki = 0; ki < 8; ki++) {
                    float xA0 = __shfl_sync(0xffffffffu, sf[ki][0], srcA);
                    float xA1 = __shfl_sync(0xffffffffu, sf[ki][1], srcA);
                    float xA2 = __shfl_sync(0xffffffffu, sf[ki][2], srcA);
                    float xA3 = __shfl_sync(0xffffffffu, sf[ki][3], srcA);
                    float xB0 = __shfl_sync(0xffffffffu, sf[ki][0], srcB);
                    float xB1 = __shfl_sync(0xffffffffu, sf[ki][1], srcB);
                    float xB2 = __shfl_sync(0xffffffffu, sf[ki][2], srcB);
                    float xB3 = __shfl_sync(0xffffffffu, sf[ki][3], srcB);
                    unsigned a0 = f32_to_tf32(par ? xA1 : xA0);
                    unsigned a1 = f32_to_tf32(par ? xA3 : xA2);
                    unsigned a2 = f32_to_tf32(par ? xB1 : xB0);
                    unsigned a3 = f32_to_tf32(par ? xB3 : xB2);
#pragma unroll
                    for (int nd = 0; nd < 8; nd++) {
                        unsigned b0 = __float_as_uint(Vs[(ki * 8 + tig) * VLDT + nd * 8 + gid]);
                        unsigned b1 = __float_as_uint(Vs[(ki * 8 + tig + 4) * VLDT + nd * 8 + gid]);
                        MMA_TF32(oacc[nd], a0, a1, a2, a3, b0, b1);
                    }
                }
            }
            buf ^= 1;
        }

        float inv0 = 1.0f / l0;
        float inv1 = 1.0f / l1;
        int rA = r0g + gid;
        int rB = rA + 8;
#pragma unroll
        for (int nd = 0; nd < 8; nd++) {
            int col = nd * 8 + 2 * tig;
            *(float2*)(O + ((size_t)(b * S_ + rA) * H_ + h) * HD_ + col) = make_float2(
                round_tf32f(oacc[nd][0] * inv0), round_tf32f(oacc[nd][1] * inv0));
            *(float2*)(O + ((size_t)(b * S_ + rB) * H_ + h) * HD_ + col) = make_float2(
                round_tf32f(oacc[nd][2] * inv1), round_tf32f(oacc[nd][3] * inv1));
        }
    }
}

// ---------------------------------------------------------------------------
// Launch (3 launches)
// ---------------------------------------------------------------------------
extern "C" void kernel_launch(void* const* d_in, const int* in_sizes, int n_in,
                              void* d_out, int out_size) {
    const float* x = (const float*)d_in[0];
    const float* cosb = (const float*)d_in[1];
    const float* sinb = (const float*)d_in[2];
    const float* wq = (const float*)d_in[4];
    const float* wk = (const float*)d_in[5];
    const float* wv = (const float*)d_in[6];
    const float* wo = (const float*)d_in[7];
    float* out = (float*)d_out;

    float *qkv, *o;
    cudaGetSymbolAddress((void**)&qkv, g_qkv);
    cudaGetSymbolAddress((void**)&o, g_o);

    const int K = DIM_;

    cudaFuncSetAttribute(flash_mma, cudaFuncAttributeMaxDynamicSharedMemorySize,
                         FL_SMEM);

    // 1: fused QKV GEMM (+RoPE, tf32-round, q pre-scale). Weights selected
    //    per output segment inside the kernel; x rounded in-loop via cvt.
    dim3 qkv_grid(NQKV / 128, (B_ * S_) / 128);   // (24, 32)
    gemm_tf32<<<qkv_grid, 256>>>(x, wq, wk, wv, qkv, NQKV, K, 1, cosb, sinb);

    // 2: flash attention (balanced complementary-block pairing)
    dim3 attn_grid(S_ / 256, H_, B_);             // (8, 16, 2)
    flash_mma<<<attn_grid, 256, FL_SMEM>>>(qkv, o);

    // 3: output GEMM
    dim3 out_grid(DIM_ / 128, (B_ * S_) / 128);   // (8, 32)
    gemm_tf32<<<out_grid, 256>>>(o, wo, wo, wo, out, DIM_, K, 0, cosb, sinb);
}

// round 15
// speedup vs baseline: 1.3079x; 1.3079x over previous
#include <cuda_runtime.h>
#include <cuda_bf16.h>
#include <cstdint>
#include <math.h>

#define B_ 2
#define S_ 2048
#define DIM_ 1024
#define H_ 16
#define HD_ 64
#define HALF_ 32
#define NQKV 3072

__device__ float g_qkv[B_ * S_ * NQKV];    // fused q|k|v (tf32-rounded, q pre-scaled)
__device__ float g_o[B_ * S_ * DIM_];
__device__ float g_x[B_ * S_ * DIM_];      // tf32-rounded x
__device__ float g_w4[4 * DIM_ * DIM_];    // tf32-rounded wq,wk,wv (stacked) + wo

__device__ __forceinline__ unsigned f32_to_tf32(float x) {
    unsigned r;
    asm("cvt.rna.tf32.f32 %0, %1;" : "=r"(r) : "f"(x));
    return r;
}
__device__ __forceinline__ float round_tf32f(float x) {
    return __uint_as_float(f32_to_tf32(x));
}

__device__ __forceinline__ uint32_t smem_to_u32(const void* p) {
    uint32_t a;
    asm("{ .reg .u64 t; cvta.to.shared.u64 t, %1; cvt.u32.u64 %0, t; }"
        : "=r"(a) : "l"(p));
    return a;
}

#define CP_ASYNC16(dst_u32, src_ptr) \
    asm volatile("cp.async.cg.shared.global [%0], [%1], 16;" :: "r"(dst_u32), "l"(src_ptr))
#define CP_COMMIT() asm volatile("cp.async.commit_group;" ::: "memory")
#define CP_WAIT(n) asm volatile("cp.async.wait_group %0;" :: "n"(n) : "memory")

#define MMA_TF32(acc, a0, a1, a2, a3, b0, b1)                                  \
    asm volatile(                                                              \
        "mma.sync.aligned.m16n8k8.row.col.f32.tf32.tf32.f32 "                  \
        "{%0,%1,%2,%3}, {%4,%5,%6,%7}, {%8,%9}, {%0,%1,%2,%3};"                \
        : "+f"(acc[0]), "+f"(acc[1]), "+f"(acc[2]), "+f"(acc[3])               \
        : "r"(a0), "r"(a1), "r"(a2), "r"(a3), "r"(b0), "r"(b1))

// ---------------------------------------------------------------------------
// tf32 rounding pre-passes
// ---------------------------------------------------------------------------
__global__ void round_tf32_kernel(const float* __restrict__ src,
                                  float* __restrict__ dst, int n4) {
    int i = blockIdx.x * blockDim.x + threadIdx.x;
    if (i >= n4) return;
    float4 v = ((const float4*)src)[i];
    ((float4*)dst)[i] = make_float4(round_tf32f(v.x), round_tf32f(v.y),
                                    round_tf32f(v.z), round_tf32f(v.w));
}

__global__ void round_w4_kernel(const float* __restrict__ w0,
                                const float* __restrict__ w1,
                                const float* __restrict__ w2,
                                const float* __restrict__ w3,
                                float* __restrict__ dst) {
    const int nw4 = (DIM_ * DIM_) / 4;
    int i = blockIdx.x * blockDim.x + threadIdx.x;
    if (i >= 4 * nw4) return;
    int seg = i / nw4;
    int off = i - seg * nw4;
    const float* src = (seg == 0) ? w0 : (seg == 1) ? w1 : (seg == 2) ? w2 : w3;
    float4 v = ((const float4*)src)[off];
    ((float4*)dst)[i] = make_float4(round_tf32f(v.x), round_tf32f(v.y),
                                    round_tf32f(v.z), round_tf32f(v.w));
}

// ---------------------------------------------------------------------------
// TF32 mma.sync GEMM (scalar fragment LDS), cp.async double-buffered,
// __launch_bounds__(256,2) => 128 regs, 2 CTAs/SM (load-bearing for latency).
// mode=1: RoPE on cols<2048, round outputs to tf32, pre-scale q by 0.125.
// ---------------------------------------------------------------------------
#define BKG 32
#define LDT 36
#define TILE_FLOATS (128 * LDT)
#define STAGE_FLOATS (2 * TILE_FLOATS)
#define GEMM_SMEM (2 * STAGE_FLOATS * 4)   // 73728 B

__global__ void __launch_bounds__(256, 2) gemm_tf32p(const float* __restrict__ A,
                                                     const float* __restrict__ Bm,
                                                     float* __restrict__ C,
                                                     int NS, int K, int mode,
                                                     const float* __restrict__ cosb,
                                                     const float* __restrict__ sinb) {
    extern __shared__ float sm[];
    const uint32_t smem_base = smem_to_u32(sm);

    const int tid = threadIdx.x;
    const int wid = tid >> 5;
    const int lane = tid & 31;
    const int gid = lane >> 2;
    const int tig = lane & 3;
    const int warp_m = wid >> 2;
    const int warp_n = wid & 3;
    const int bx = blockIdx.x;
    const int by = blockIdx.y;

    const float* Ab = A + (size_t)(by * 128) * K;
    const float* Bb = Bm + (size_t)(bx * 128) * K;

    const int crow = tid >> 3;
    const int cc4 = tid & 7;

    auto issue_copy = [&](int c, int s) {
        uint32_t abase = smem_base + (uint32_t)(s * STAGE_FLOATS) * 4;
        uint32_t bbase = abase + (uint32_t)TILE_FLOATS * 4;
        const float* Ap = Ab + c * BKG;
        const float* Bp = Bb + c * BKG;
#pragma unroll
        for (int i = 0; i < 4; i++) {
            int row = crow + i * 32;
            uint32_t off = (uint32_t)(row * LDT + cc4 * 4) * 4;
            CP_ASYNC16(abase + off, Ap + (size_t)row * K + cc4 * 4);
            CP_ASYNC16(bbase + off, Bp + (size_t)row * K + cc4 * 4);
        }
    };

    float acc[4][4][4];
#pragma unroll
    for (int mi = 0; mi < 4; mi++)
#pragma unroll
        for (int ni = 0; ni < 4; ni++)
#pragma unroll
            for (int c = 0; c < 4; c++) acc[mi][ni][c] = 0.0f;

    const int nchunks = K / BKG;
    issue_copy(0, 0);
    CP_COMMIT();

#pragma unroll 1
    for (int c = 0; c < nchunks; c++) {
        const int s = c & 1;
        if (c + 1 < nchunks) {
            issue_copy(c + 1, s ^ 1);
            CP_COMMIT();
            CP_WAIT(1);
        } else {
            CP_WAIT(0);
        }
        __syncthreads();

        const unsigned* As = (const unsigned*)(sm + s * STAGE_FLOATS);
        const unsigned* Bs = (const unsigned*)(sm + s * STAGE_FLOATS + TILE_FLOATS);

#pragma unroll
        for (int ks = 0; ks < BKG; ks += 8) {
            unsigned a[4][4], b[4][2];
#pragma unroll
            for (int mi = 0; mi < 4; mi++) {
                int r = warp_m * 64 + mi * 16 + gid;
                int cc = ks + tig;
                a[mi][0] = As[r * LDT + cc];
                a[mi][1] = As[(r + 8) * LDT + cc];
                a[mi][2] = As[r * LDT + cc + 4];
                a[mi][3] = As[(r + 8) * LDT + cc + 4];
            }
#pragma unroll
            for (int ni = 0; ni < 4; ni++) {
                int n = warp_n * 32 + ni * 8 + gid;
                int cc = ks + tig;
                b[ni][0] = Bs[n * LDT + cc];
                b[ni][1] = Bs[n * LDT + cc + 4];
            }
#pragma unroll
            for (int mi = 0; mi < 4; mi++)
#pragma unroll
                for (int ni = 0; ni < 4; ni++)
                    MMA_TF32(acc[mi][ni], a[mi][0], a[mi][1], a[mi][2], a[mi][3],
                             b[ni][0], b[ni][1]);
        }
        __syncthreads();
    }

#pragma unroll
    for (int mi = 0; mi < 4; mi++) {
#pragma unroll
        for (int ni = 0; ni < 4; ni++) {
            int rA = by * 128 + warp_m * 64 + mi * 16 + gid;
            int rB = rA + 8;
            int cc = bx * 128 + warp_n * 32 + ni * 8 + 2 * tig;
            float e0 = acc[mi][ni][0], o0 = acc[mi][ni][1];
            float e1 = acc[mi][ni][2], o1 = acc[mi][ni][3];
            if (mode) {
                if (cc < 2048) {
                    int p = (cc & 63) >> 1;
                    float cA = cosb[(rA & (S_ - 1)) * HALF_ + p];
                    float sA = sinb[(rA & (S_ - 1)) * HALF_ + p];
                    float cB = cosb[(rB & (S_ - 1)) * HALF_ + p];
                    float sB = sinb[(rB & (S_ - 1)) * HALF_ + p];
                    float t0 = e0 * cA - o0 * sA, t1 = e0 * sA + o0 * cA;
                    e0 = t0; o0 = t1;
                    float t2 = e1 * cB - o1 * sB, t3 = e1 * sB + o1 * cB;
                    e1 = t2; o1 = t3;
                }
                float sc = (cc < 1024) ? 0.125f : 1.0f;
                e0 = round_tf32f(e0 * sc); o0 = round_tf32f(o0 * sc);
                e1 = round_tf32f(e1 * sc); o1 = round_tf32f(o1 * sc);
            }
            *(float2*)(C + (size_t)rA * NS + cc) = make_float2(e0, o0);
            *(float2*)(C + (size_t)rB * NS + cc) = make_float2(e1, o1);
        }
    }
}

// ---------------------------------------------------------------------------
// Flash attention, tf32 mma, cp.async double-buffered K/V tiles, balanced
// complementary-pair scheduling: each CTA does query blocks (15-bx) then bx,
// 32 key-tile units per CTA, 256 CTAs = one balanced wave.
// ---------------------------------------------------------------------------
#define KLDT 68
#define VLDT 72
#define KTILE (64 * KLDT)
#define VTILE (64 * VLDT)
#define FL_SMEM ((2 * KTILE + 2 * VTILE) * 4)   // 70656 B

__global__ void __launch_bounds__(256, 2) flash_mma(const float* __restrict__ QKV,
                                                    float* __restrict__ O) {
    extern __shared__ float sm[];
    const uint32_t smem_base = smem_to_u32(sm);
    float* Kbuf[2] = {sm, sm + KTILE};
    float* Vbuf[2] = {sm + 2 * KTILE, sm + 2 * KTILE + VTILE};

    const int tid = threadIdx.x;
    const int wid = tid >> 5;
    const int lane = tid & 31;
    const int gid = lane >> 2;
    const int tig = lane & 3;
    const int bx = blockIdx.x;        // 0..7
    const int h = blockIdx.y;
    const int b = blockIdx.z;

    const int srcA = (lane & ~3) | (tig >> 1);
    const int srcB = srcA + 2;
    const int par = tig & 1;

    const int crow = tid >> 4;
    const int cc4 = tid & 15;

    auto issue_tile = [&](int kt, int s) {
        uint32_t kb = smem_base + (uint32_t)(s * KTILE) * 4;
        uint32_t vb = smem_base + (uint32_t)(2 * KTILE + s * VTILE) * 4;
#pragma unroll
        for (int i = 0; i < 4; i++) {
            int row = crow + i * 16;
            size_t g = (size_t)(b * S_ + kt + row) * NQKV + h * HD_ + cc4 * 4;
            CP_ASYNC16(kb + (uint32_t)(row * KLDT + cc4 * 4) * 4, QKV + g + 1024);
            CP_ASYNC16(vb + (uint32_t)(row * VLDT + cc4 * 4) * 4, QKV + g + 2048);
        }
    };

#pragma unroll 1
    for (int pass = 0; pass < 2; pass++) {
        const int qb = pass ? bx : (15 - bx);   // heavy block first
        const int qbase = qb * 128;

        __syncthreads();

        // Stage Q tile into K region, pull fragments
#pragma unroll
        for (int i = 0; i < 8; i++) {
            int lin = tid + i * 256;
            int row = lin >> 4;
            int c4 = lin & 15;
            *(float4*)(&sm[row * KLDT + c4 * 4]) =
                *(const float4*)(QKV + (size_t)(b * S_ + qbase + row) * NQKV + h * HD_ + c4 * 4);
        }
        __syncthreads();

        const int r0 = wid * 16;
        unsigned qf[8][4];
#pragma unroll
        for (int ks = 0; ks < 8; ks++) {
            int c = ks * 8 + tig;
            qf[ks][0] = __float_as_uint(sm[(r0 + gid) * KLDT + c]);
            qf[ks][1] = __float_as_uint(sm[(r0 + gid + 8) * KLDT + c]);
            qf[ks][2] = __float_as_uint(sm[(r0 + gid) * KLDT + c + 4]);
            qf[ks][3] = __float_as_uint(sm[(r0 + gid + 8) * KLDT + c + 4]);
        }
        __syncthreads();

        float oacc[8][4];
#pragma unroll
        for (int nd = 0; nd < 8; nd++)
#pragma unroll
            for (int c = 0; c < 4; c++) oacc[nd][c] = 0.0f;
        float m0 = -1e30f, m1 = -1e30f, l0 = 0.0f, l1 = 0.0f;

        const int r0g = qbase + r0;
        const int kend = qbase + 128;

        issue_tile(0, 0);
        CP_COMMIT();

        int buf = 0;
#pragma unroll 1
        for (int kt = 0; kt < kend; kt += 64) {
            CP_WAIT(0);
            __syncthreads();
            if (kt + 64 < kend) {
                issue_tile(kt + 64, buf ^ 1);
                CP_COMMIT();
            }

            if (kt <= r0g + 15) {
                const float* Ks = Kbuf[buf];
                const float* Vs = Vbuf[buf];

                float sf[8][4];
#pragma unroll
                for (int nt = 0; nt < 8; nt++) {
                    sf[nt][0] = 0.0f; sf[nt][1] = 0.0f;
                    sf[nt][2] = 0.0f; sf[nt][3] = 0.0f;
#pragma unroll
                    for (int ks = 0; ks < 8; ks++) {
                        unsigned b0 = __float_as_uint(Ks[(nt * 8 + gid) * KLDT + ks * 8 + tig]);
                        unsigned b1 = __float_as_uint(Ks[(nt * 8 + gid) * KLDT + ks * 8 + tig + 4]);
                        MMA_TF32(sf[nt], qf[ks][0], qf[ks][1], qf[ks][2], qf[ks][3], b0, b1);
                    }
                }

                if (kt + 63 > r0g) {
                    int rA = r0g + gid;
                    int rB = rA + 8;
#pragma unroll
                    for (int nt = 0; nt < 8; nt++) {
                        int colb = kt + nt * 8 + 2 * tig;
                        if (colb > rA) sf[nt][0] = -1e30f;
                        if (colb + 1 > rA) sf[nt][1] = -1e30f;
                        if (colb > rB) sf[nt][2] = -1e30f;
                        if (colb + 1 > rB) sf[nt][3] = -1e30f;
                    }
                }

                float mx0 = m0, mx1 = m1;
#pragma unroll
                for (int nt = 0; nt < 8; nt++) {
                    mx0 = fmaxf(mx0, fmaxf(sf[nt][0], sf[nt][1]));
                    mx1 = fmaxf(mx1, fmaxf(sf[nt][2], sf[nt][3]));
                }
                mx0 = fmaxf(mx0, __shfl_xor_sync(0xffffffffu, mx0, 1));
                mx0 = fmaxf(mx0, __shfl_xor_sync(0xffffffffu, mx0, 2));
                mx1 = fmaxf(mx1, __shfl_xor_sync(0xffffffffu, mx1, 1));
                mx1 = fmaxf(mx1, __shfl_xor_sync(0xffffffffu, mx1, 2));

                float corr0 = __expf(m0 - mx0);
                float corr1 = __expf(m1 - mx1);
                float rs0 = 0.0f, rs1 = 0.0f;
#pragma unroll
                for (int nt = 0; nt < 8; nt++) {
                    sf[nt][0] = __expf(sf[nt][0] - mx0);
                    sf[nt][1] = __expf(sf[nt][1] - mx0);
                    sf[nt][2] = __expf(sf[nt][2] - mx1);
                    sf[nt][3] = __expf(sf[nt][3] - mx1);
                    rs0 += sf[nt][0] + sf[nt][1];
                    rs1 += sf[nt][2] + sf[nt][3];
                }
                rs0 += __shfl_xor_sync(0xffffffffu, rs0, 1);
                rs0 += __shfl_xor_sync(0xffffffffu, rs0, 2);
                rs1 += __shfl_xor_sync(0xffffffffu, rs1, 1);
                rs1 += __shfl_xor_sync(0xffffffffu, rs1, 2);
                l0 = l0 * corr0 + rs0;
                l1 = l1 * corr1 + rs1;
                m0 = mx0; m1 = mx1;
#pragma unroll
                for (int nd = 0; nd < 8; nd++) {
                    oacc[nd][0] *= corr0; oacc[nd][1] *= corr0;
                    oacc[nd][2] *= corr1; oacc[nd][3] *= corr1;
                }

#pragma unroll
                for (int ki = 0; ki < 8; ki++) {
                    float xA0 = __shfl_sync(0xffffffffu, sf[ki][0], srcA);
                    float xA1 = __shfl_sync(0xffffffffu, sf[ki][1], srcA);
                    float xA2 = __shfl_sync(0xffffffffu, sf[ki][2], srcA);
                    float xA3 = __shfl_sync(0xffffffffu, sf[ki][3], srcA);
                    float xB0 = __shfl_sync(0xffffffffu, sf[ki][0], srcB);
                    float xB1 = __shfl_sync(0xffffffffu, sf[ki][1], srcB);
                    float xB2 = __shfl_sync(0xffffffffu, sf[ki][2], srcB);
                    float xB3 = __shfl_sync(0xffffffffu, sf[ki][3], srcB);
                    unsigned a0 = f32_to_tf32(par ? xA1 : xA0);
                    unsigned a1 = f32_to_tf32(par ? xA3 : xA2);
                    unsigned a2 = f32_to_tf32(par ? xB1 : xB0);
                    unsigned a3 = f32_to_tf32(par ? xB3 : xB2);
#pragma unroll
                    for (int nd = 0; nd < 8; nd++) {
                        unsigned b0 = __float_as_uint(Vs[(ki * 8 + tig) * VLDT + nd * 8 + gid]);
                        unsigned b1 = __float_as_uint(Vs[(ki * 8 + tig + 4) * VLDT + nd * 8 + gid]);
                        MMA_TF32(oacc[nd], a0, a1, a2, a3, b0, b1);
                    }
                }
            }
            buf ^= 1;
        }

        float inv0 = 1.0f / l0;
        float inv1 = 1.0f / l1;
        int rA = r0g + gid;
        int rB = rA + 8;
#pragma unroll
        for (int nd = 0; nd < 8; nd++) {
            int col = nd * 8 + 2 * tig;
            *(float2*)(O + ((size_t)(b * S_ + rA) * H_ + h) * HD_ + col) = make_float2(
                round_tf32f(oacc[nd][0] * inv0), round_tf32f(oacc[nd][1] * inv0));
            *(float2*)(O + ((size_t)(b * S_ + rB) * H_ + h) * HD_ + col) = make_float2(
                round_tf32f(oacc[nd][2] * inv1), round_tf32f(oacc[nd][3] * inv1));
        }
    }
}

// ---------------------------------------------------------------------------
// Launch (5 launches)
// ---------------------------------------------------------------------------
extern "C" void kernel_launch(void* const* d_in, const int* in_sizes, int n_in,
                              void* d_out, int out_size) {
    const float* x = (const float*)d_in[0];
    const float* cosb = (const float*)d_in[1];
    const float* sinb = (const float*)d_in[2];
    const float* wq = (const float*)d_in[4];
    const float* wk = (const float*)d_in[5];
    const float* wv = (const float*)d_in[6];
    const float* wo = (const float*)d_in[7];
    float* out = (float*)d_out;

    float *qkv, *o, *xr, *w4;
    cudaGetSymbolAddress((void**)&qkv, g_qkv);
    cudaGetSymbolAddress((void**)&o, g_o);
    cudaGetSymbolAddress((void**)&xr, g_x);
    cudaGetSymbolAddress((void**)&w4, g_w4);
    float* wor = w4 + 3 * DIM_ * DIM_;

    const int K = DIM_;

    cudaFuncSetAttribute(gemm_tf32p, cudaFuncAttributeMaxDynamicSharedMemorySize,
                         GEMM_SMEM);
    cudaFuncSetAttribute(flash_mma, cudaFuncAttributeMaxDynamicSharedMemorySize,
                         FL_SMEM);

    int nx4 = (B_ * S_ * DIM_) / 4;
    int nw4all = DIM_ * DIM_;
    round_tf32_kernel<<<nx4 / 256, 256>>>(x, xr, nx4);
    round_w4_kernel<<<nw4all / 256, 256>>>(wq, wk, wv, wo, w4);

    dim3 qkv_grid(NQKV / 128, (B_ * S_) / 128);   // (24, 32)
    gemm_tf32p<<<qkv_grid, 256, GEMM_SMEM>>>(xr, w4, qkv, NQKV, K, 1, cosb, sinb);

    dim3 attn_grid(S_ / 256, H_, B_);             // (8, 16, 2) balanced pairs
    flash_mma<<<attn_grid, 256, FL_SMEM>>>(qkv, o);

    dim3 out_grid(DIM_ / 128, (B_ * S_) / 128);   // (8, 32)
    gemm_tf32p<<<out_grid, 256, GEMM_SMEM>>>(o, wor, out, DIM_, K, 0, cosb, sinb);
}

// round 16
// speedup vs baseline: 1.3086x; 1.0005x over previous
#include <cuda_runtime.h>
#include <cuda_bf16.h>
#include <cstdint>
#include <math.h>

#define B_ 2
#define S_ 2048
#define DIM_ 1024
#define H_ 16
#define HD_ 64
#define HALF_ 32
#define NQKV 3072

__device__ float g_qkv[B_ * S_ * NQKV];    // fused q|k|v (tf32-rounded, q pre-scaled)
__device__ float g_o[B_ * S_ * DIM_];
__device__ float g_x[B_ * S_ * DIM_];      // tf32-rounded x
__device__ float g_w4[4 * DIM_ * DIM_];    // tf32-rounded wq,wk,wv (stacked) + wo

__device__ __forceinline__ unsigned f32_to_tf32(float x) {
    unsigned r;
    asm("cvt.rna.tf32.f32 %0, %1;" : "=r"(r) : "f"(x));
    return r;
}
__device__ __forceinline__ float round_tf32f(float x) {
    return __uint_as_float(f32_to_tf32(x));
}

__device__ __forceinline__ uint32_t smem_to_u32(const void* p) {
    uint32_t a;
    asm("{ .reg .u64 t; cvta.to.shared.u64 t, %1; cvt.u32.u64 %0, t; }"
        : "=r"(a) : "l"(p));
    return a;
}

#define CP_ASYNC16(dst_u32, src_ptr) \
    asm volatile("cp.async.cg.shared.global [%0], [%1], 16;" :: "r"(dst_u32), "l"(src_ptr))
#define CP_COMMIT() asm volatile("cp.async.commit_group;" ::: "memory")
#define CP_WAIT(n) asm volatile("cp.async.wait_group %0;" :: "n"(n) : "memory")

#define MMA_TF32(acc, a0, a1, a2, a3, b0, b1)                                  \
    asm volatile(                                                              \
        "mma.sync.aligned.m16n8k8.row.col.f32.tf32.tf32.f32 "                  \
        "{%0,%1,%2,%3}, {%4,%5,%6,%7}, {%8,%9}, {%0,%1,%2,%3};"                \
        : "+f"(acc[0]), "+f"(acc[1]), "+f"(acc[2]), "+f"(acc[3])               \
        : "r"(a0), "r"(a1), "r"(a2), "r"(a3), "r"(b0), "r"(b1))

// ---------------------------------------------------------------------------
// tf32 rounding pre-passes
// ---------------------------------------------------------------------------
__global__ void round_tf32_kernel(const float* __restrict__ src,
                                  float* __restrict__ dst, int n4) {
    int i = blockIdx.x * blockDim.x + threadIdx.x;
    if (i >= n4) return;
    float4 v = ((const float4*)src)[i];
    ((float4*)dst)[i] = make_float4(round_tf32f(v.x), round_tf32f(v.y),
                                    round_tf32f(v.z), round_tf32f(v.w));
}

__global__ void round_w4_kernel(const float* __restrict__ w0,
                                const float* __restrict__ w1,
                                const float* __restrict__ w2,
                                const float* __restrict__ w3,
                                float* __restrict__ dst) {
    const int nw4 = (DIM_ * DIM_) / 4;
    int i = blockIdx.x * blockDim.x + threadIdx.x;
    if (i >= 4 * nw4) return;
    int seg = i / nw4;
    int off = i - seg * nw4;
    const float* src = (seg == 0) ? w0 : (seg == 1) ? w1 : (seg == 2) ? w2 : w3;
    float4 v = ((const float4*)src)[off];
    ((float4*)dst)[i] = make_float4(round_tf32f(v.x), round_tf32f(v.y),
                                    round_tf32f(v.z), round_tf32f(v.w));
}

// ---------------------------------------------------------------------------
// TF32 mma.sync GEMM (scalar fragment LDS), cp.async double-buffered,
// __launch_bounds__(256,2) => 128 regs, 2 CTAs/SM (load-bearing for latency).
// mode=1: RoPE on cols<2048, round outputs to tf32, pre-scale q by 0.125.
// ---------------------------------------------------------------------------
#define BKG 32
#define LDT 36
#define TILE_FLOATS (128 * LDT)
#define STAGE_FLOATS (2 * TILE_FLOATS)
#define GEMM_SMEM (2 * STAGE_FLOATS * 4)   // 73728 B

__global__ void __launch_bounds__(256, 2) gemm_tf32p(const float* __restrict__ A,
                                                     const float* __restrict__ Bm,
                                                     float* __restrict__ C,
                                                     int NS, int K, int mode,
                                                     const float* __restrict__ cosb,
                                                     const float* __restrict__ sinb) {
    extern __shared__ float sm[];
    const uint32_t smem_base = smem_to_u32(sm);

    const int tid = threadIdx.x;
    const int wid = tid >> 5;
    const int lane = tid & 31;
    const int gid = lane >> 2;
    const int tig = lane & 3;
    const int warp_m = wid >> 2;
    const int warp_n = wid & 3;
    const int bx = blockIdx.x;
    const int by = blockIdx.y;

    const float* Ab = A + (size_t)(by * 128) * K;
    const float* Bb = Bm + (size_t)(bx * 128) * K;

    const int crow = tid >> 3;
    const int cc4 = tid & 7;

    auto issue_copy = [&](int c, int s) {
        uint32_t abase = smem_base + (uint32_t)(s * STAGE_FLOATS) * 4;
        uint32_t bbase = abase + (uint32_t)TILE_FLOATS * 4;
        const float* Ap = Ab + c * BKG;
        const float* Bp = Bb + c * BKG;
#pragma unroll
        for (int i = 0; i < 4; i++) {
            int row = crow + i * 32;
            uint32_t off = (uint32_t)(row * LDT + cc4 * 4) * 4;
            CP_ASYNC16(abase + off, Ap + (size_t)row * K + cc4 * 4);
            CP_ASYNC16(bbase + off, Bp + (size_t)row * K + cc4 * 4);
        }
    };

    float acc[4][4][4];
#pragma unroll
    for (int mi = 0; mi < 4; mi++)
#pragma unroll
        for (int ni = 0; ni < 4; ni++)
#pragma unroll
            for (int c = 0; c < 4; c++) acc[mi][ni][c] = 0.0f;

    const int nchunks = K / BKG;
    issue_copy(0, 0);
    CP_COMMIT();

#pragma unroll 1
    for (int c = 0; c < nchunks; c++) {
        const int s = c & 1;
        if (c + 1 < nchunks) {
            issue_copy(c + 1, s ^ 1);
            CP_COMMIT();
            CP_WAIT(1);
        } else {
            CP_WAIT(0);
        }
        __syncthreads();

        const unsigned* As = (const unsigned*)(sm + s * STAGE_FLOATS);
        const unsigned* Bs = (const unsigned*)(sm + s * STAGE_FLOATS + TILE_FLOATS);

#pragma unroll
        for (int ks = 0; ks < BKG; ks += 8) {
            unsigned a[4][4], b[4][2];
#pragma unroll
            for (int mi = 0; mi < 4; mi++) {
                int r = warp_m * 64 + mi * 16 + gid;
                int cc = ks + tig;
                a[mi][0] = As[r * LDT + cc];
                a[mi][1] = As[(r + 8) * LDT + cc];
                a[mi][2] = As[r * LDT + cc + 4];
                a[mi][3] = As[(r + 8) * LDT + cc + 4];
            }
#pragma unroll
            for (int ni = 0; ni < 4; ni++) {
                int n = warp_n * 32 + ni * 8 + gid;
                int cc = ks + tig;
                b[ni][0] = Bs[n * LDT + cc];
                b[ni][1] = Bs[n * LDT + cc + 4];
            }
#pragma unroll
            for (int mi = 0; mi < 4; mi++)
#pragma unroll
                for (int ni = 0; ni < 4; ni++)
                    MMA_TF32(acc[mi][ni], a[mi][0], a[mi][1], a[mi][2], a[mi][3],
                             b[ni][0], b[ni][1]);
        }
        __syncthreads();
    }

#pragma unroll
    for (int mi = 0; mi < 4; mi++) {
#pragma unroll
        for (int ni = 0; ni < 4; ni++) {
            int rA = by * 128 + warp_m * 64 + mi * 16 + gid;
            int rB = rA + 8;
            int cc = bx * 128 + warp_n * 32 + ni * 8 + 2 * tig;
            float e0 = acc[mi][ni][0], o0 = acc[mi][ni][1];
            float e1 = acc[mi][ni][2], o1 = acc[mi][ni][3];
            if (mode) {
                if (cc < 2048) {
                    int p = (cc & 63) >> 1;
                    float cA = cosb[(rA & (S_ - 1)) * HALF_ + p];
                    float sA = sinb[(rA & (S_ - 1)) * HALF_ + p];
                    float cB = cosb[(rB & (S_ - 1)) * HALF_ + p];
                    float sB = sinb[(rB & (S_ - 1)) * HALF_ + p];
                    float t0 = e0 * cA - o0 * sA, t1 = e0 * sA + o0 * cA;
                    e0 = t0; o0 = t1;
                    float t2 = e1 * cB - o1 * sB, t3 = e1 * sB + o1 * cB;
                    e1 = t2; o1 = t3;
                }
                float sc = (cc < 1024) ? 0.125f : 1.0f;
                e0 = round_tf32f(e0 * sc); o0 = round_tf32f(o0 * sc);
                e1 = round_tf32f(e1 * sc); o1 = round_tf32f(o1 * sc);
            }
            *(float2*)(C + (size_t)rA * NS + cc) = make_float2(e0, o0);
            *(float2*)(C + (size_t)rB * NS + cc) = make_float2(e1, o1);
        }
    }
}

// ---------------------------------------------------------------------------
// Flash attention, tf32 mma, cp.async double-buffered K/V, balanced
// complementary-pair scheduling. PV transpose via per-warp smem P-stage
// (replaces the 64-shuffle chain): cvt once, 16 STS.64, syncwarp, 32 LDS.32
// landing on the exact m16k8 A-fragment layout (reads conflict-free at
// stride 68: bank = 4*gid + tig + 8*ki).
// ---------------------------------------------------------------------------
#define KLDT 68
#define VLDT 72
#define PLDT 68
#define KTILE (64 * KLDT)
#define VTILE (64 * VLDT)
#define PBASE (2 * KTILE + 2 * VTILE)            // float offset of P region
#define PTILE (16 * PLDT)                        // per-warp P tile
#define FL_SMEM ((PBASE + 8 * PTILE) * 4)        // 70656 + 34816 = 105472 B

__global__ void __launch_bounds__(256, 2) flash_mma(const float* __restrict__ QKV,
                                                    float* __restrict__ O) {
    extern __shared__ float sm[];
    const uint32_t smem_base = smem_to_u32(sm);
    float* Kbuf[2] = {sm, sm + KTILE};
    float* Vbuf[2] = {sm + 2 * KTILE, sm + 2 * KTILE + VTILE};

    const int tid = threadIdx.x;
    const int wid = tid >> 5;
    const int lane = tid & 31;
    const int gid = lane >> 2;
    const int tig = lane & 3;
    const int bx = blockIdx.x;        // 0..7
    const int h = blockIdx.y;
    const int b = blockIdx.z;

    float* Pw = sm + PBASE + wid * PTILE;   // private 16x64, stride 68

    const int crow = tid >> 4;
    const int cc4 = tid & 15;

    auto issue_tile = [&](int kt, int s) {
        uint32_t kb = smem_base + (uint32_t)(s * KTILE) * 4;
        uint32_t vb = smem_base + (uint32_t)(2 * KTILE + s * VTILE) * 4;
#pragma unroll
        for (int i = 0; i < 4; i++) {
            int row = crow + i * 16;
            size_t g = (size_t)(b * S_ + kt + row) * NQKV + h * HD_ + cc4 * 4;
            CP_ASYNC16(kb + (uint32_t)(row * KLDT + cc4 * 4) * 4, QKV + g + 1024);
            CP_ASYNC16(vb + (uint32_t)(row * VLDT + cc4 * 4) * 4, QKV + g + 2048);
        }
    };

#pragma unroll 1
    for (int pass = 0; pass < 2; pass++) {
        const int qb = pass ? bx : (15 - bx);   // heavy block first
        const int qbase = qb * 128;

        __syncthreads();

        // Stage Q tile into K region, pull fragments
#pragma unroll
        for (int i = 0; i < 8; i++) {
            int lin = tid + i * 256;
            int row = lin >> 4;
            int c4 = lin & 15;
            *(float4*)(&sm[row * KLDT + c4 * 4]) =
                *(const float4*)(QKV + (size_t)(b * S_ + qbase + row) * NQKV + h * HD_ + c4 * 4);
        }
        __syncthreads();

        const int r0 = wid * 16;
        unsigned qf[8][4];
#pragma unroll
        for (int ks = 0; ks < 8; ks++) {
            int c = ks * 8 + tig;
            qf[ks][0] = __float_as_uint(sm[(r0 + gid) * KLDT + c]);
            qf[ks][1] = __float_as_uint(sm[(r0 + gid + 8) * KLDT + c]);
            qf[ks][2] = __float_as_uint(sm[(r0 + gid) * KLDT + c + 4]);
            qf[ks][3] = __float_as_uint(sm[(r0 + gid + 8) * KLDT + c + 4]);
        }
        __syncthreads();

        float oacc[8][4];
#pragma unroll
        for (int nd = 0; nd < 8; nd++)
#pragma unroll
            for (int c = 0; c < 4; c++) oacc[nd][c] = 0.0f;
        float m0 = -1e30f, m1 = -1e30f, l0 = 0.0f, l1 = 0.0f;

        const int r0g = qbase + r0;
        const int kend = qbase + 128;

        issue_tile(0, 0);
        CP_COMMIT();

        int buf = 0;
#pragma unroll 1
        for (int kt = 0; kt < kend; kt += 64) {
            CP_WAIT(0);
            __syncthreads();
            if (kt + 64 < kend) {
                issue_tile(kt + 64, buf ^ 1);
                CP_COMMIT();
            }

            if (kt <= r0g + 15) {
                const float* Ks = Kbuf[buf];
                const float* Vs = Vbuf[buf];

                float sf[8][4];
#pragma unroll
                for (int nt = 0; nt < 8; nt++) {
                    sf[nt][0] = 0.0f; sf[nt][1] = 0.0f;
                    sf[nt][2] = 0.0f; sf[nt][3] = 0.0f;
#pragma unroll
                    for (int ks = 0; ks < 8; ks++) {
                        unsigned b0 = __float_as_uint(Ks[(nt * 8 + gid) * KLDT + ks * 8 + tig]);
                        unsigned b1 = __float_as_uint(Ks[(nt * 8 + gid) * KLDT + ks * 8 + tig + 4]);
                        MMA_TF32(sf[nt], qf[ks][0], qf[ks][1], qf[ks][2], qf[ks][3], b0, b1);
                    }
                }

                if (kt + 63 > r0g) {
                    int rA = r0g + gid;
                    int rB = rA + 8;
#pragma unroll
                    for (int nt = 0; nt < 8; nt++) {
                        int colb = kt + nt * 8 + 2 * tig;
                        if (colb > rA) sf[nt][0] = -1e30f;
                        if (colb + 1 > rA) sf[nt][1] = -1e30f;
                        if (colb > rB) sf[nt][2] = -1e30f;
                        if (colb + 1 > rB) sf[nt][3] = -1e30f;
                    }
                }

                float mx0 = m0, mx1 = m1;
#pragma unroll
                for (int nt = 0; nt < 8; nt++) {
                    mx0 = fmaxf(mx0, fmaxf(sf[nt][0], sf[nt][1]));
                    mx1 = fmaxf(mx1, fmaxf(sf[nt][2], sf[nt][3]));
                }
                mx0 = fmaxf(mx0, __shfl_xor_sync(0xffffffffu, mx0, 1));
                mx0 = fmaxf(mx0, __shfl_xor_sync(0xffffffffu, mx0, 2));
                mx1 = fmaxf(mx1, __shfl_xor_sync(0xffffffffu, mx1, 1));
                mx1 = fmaxf(mx1, __shfl_xor_sync(0xffffffffu, mx1, 2));

                float corr0 = __expf(m0 - mx0);
                float corr1 = __expf(m1 - mx1);
                float rs0 = 0.0f, rs1 = 0.0f;
#pragma unroll
                for (int nt = 0; nt < 8; nt++) {
                    sf[nt][0] = __expf(sf[nt][0] - mx0);
                    sf[nt][1] = __expf(sf[nt][1] - mx0);
                    sf[nt][2] = __expf(sf[nt][2] - mx1);
                    sf[nt][3] = __expf(sf[nt][3] - mx1);
                    rs0 += sf[nt][0] + sf[nt][1];
                    rs1 += sf[nt][2] + sf[nt][3];
                }
                rs0 += __shfl_xor_sync(0xffffffffu, rs0, 1);
                rs0 += __shfl_xor_sync(0xffffffffu, rs0, 2);
                rs1 += __shfl_xor_sync(0xffffffffu, rs1, 1);
                rs1 += __shfl_xor_sync(0xffffffffu, rs1, 2);
                l0 = l0 * corr0 + rs0;
                l1 = l1 * corr1 + rs1;
                m0 = mx0; m1 = mx1;
#pragma unroll
                for (int nd = 0; nd < 8; nd++) {
                    oacc[nd][0] *= corr0; oacc[nd][1] *= corr0;
                    oacc[nd][2] *= corr1; oacc[nd][3] *= corr1;
                }

                // Stage P (tf32-rounded) into private smem tile
#pragma unroll
                for (int nt = 0; nt < 8; nt++) {
                    int c = nt * 8 + 2 * tig;
                    *(float2*)(&Pw[gid * PLDT + c]) =
                        make_float2(round_tf32f(sf[nt][0]), round_tf32f(sf[nt][1]));
                    *(float2*)(&Pw[(gid + 8) * PLDT + c]) =
                        make_float2(round_tf32f(sf[nt][2]), round_tf32f(sf[nt][3]));
                }
                __syncwarp();

                // O += P @ V : A-frags straight from P tile, conflict-free
#pragma unroll
                for (int ki = 0; ki < 8; ki++) {
                    int c = ki * 8 + tig;
                    unsigned a0 = __float_as_uint(Pw[gid * PLDT + c]);
                    unsigned a1 = __float_as_uint(Pw[(gid + 8) * PLDT + c]);
                    unsigned a2 = __float_as_uint(Pw[gid * PLDT + c + 4]);
                    unsigned a3 = __float_as_uint(Pw[(gid + 8) * PLDT + c + 4]);
#pragma unroll
                    for (int nd = 0; nd < 8; nd++) {
                        unsigned b0 = __float_as_uint(Vs[(ki * 8 + tig) * VLDT + nd * 8 + gid]);
                        unsigned b1 = __float_as_uint(Vs[(ki * 8 + tig + 4) * VLDT + nd * 8 + gid]);
                        MMA_TF32(oacc[nd], a0, a1, a2, a3, b0, b1);
                    }
                }
                __syncwarp();
            }
            buf ^= 1;
        }

        float inv0 = 1.0f / l0;
        float inv1 = 1.0f / l1;
        int rA = r0g + gid;
        int rB = rA + 8;
#pragma unroll
        for (int nd = 0; nd < 8; nd++) {
            int col = nd * 8 + 2 * tig;
            *(float2*)(O + ((size_t)(b * S_ + rA) * H_ + h) * HD_ + col) = make_float2(
                round_tf32f(oacc[nd][0] * inv0), round_tf32f(oacc[nd][1] * inv0));
            *(float2*)(O + ((size_t)(b * S_ + rB) * H_ + h) * HD_ + col) = make_float2(
                round_tf32f(oacc[nd][2] * inv1), round_tf32f(oacc[nd][3] * inv1));
        }
    }
}

// ---------------------------------------------------------------------------
// Launch (5 launches)
// ---------------------------------------------------------------------------
extern "C" void kernel_launch(void* const* d_in, const int* in_sizes, int n_in,
                              void* d_out, int out_size) {
    const float* x = (const float*)d_in[0];
    const float* cosb = (const float*)d_in[1];
    const float* sinb = (const float*)d_in[2];
    const float* wq = (const float*)d_in[4];
    const float* wk = (const float*)d_in[5];
    const float* wv = (const float*)d_in[6];
    const float* wo = (const float*)d_in[7];
    float* out = (float*)d_out;

    float *qkv, *o, *xr, *w4;
    cudaGetSymbolAddress((void**)&qkv, g_qkv);
    cudaGetSymbolAddress((void**)&o, g_o);
    cudaGetSymbolAddress((void**)&xr, g_x);
    cudaGetSymbolAddress((void**)&w4, g_w4);
    float* wor = w4 + 3 * DIM_ * DIM_;

    const int K = DIM_;

    cudaFuncSetAttribute(gemm_tf32p, cudaFuncAttributeMaxDynamicSharedMemorySize,
                         GEMM_SMEM);
    cudaFuncSetAttribute(flash_mma, cudaFuncAttributeMaxDynamicSharedMemorySize,
                         FL_SMEM);

    int nx4 = (B_ * S_ * DIM_) / 4;
    int nw4all = DIM_ * DIM_;
    round_tf32_kernel<<<nx4 / 256, 256>>>(x, xr, nx4);
    round_w4_kernel<<<nw4all / 256, 256>>>(wq, wk, wv, wo, w4);

    dim3 qkv_grid(NQKV / 128, (B_ * S_) / 128);   // (24, 32)
    gemm_tf32p<<<qkv_grid, 256, GEMM_SMEM>>>(xr, w4, qkv, NQKV, K, 1, cosb, sinb);

    dim3 attn_grid(S_ / 256, H_, B_);             // (8, 16, 2) balanced pairs
    flash_mma<<<attn_grid, 256, FL_SMEM>>>(qkv, o);

    dim3 out_grid(DIM_ / 128, (B_ * S_) / 128);   // (8, 32)
    gemm_tf32p<<<out_grid, 256, GEMM_SMEM>>>(o, wor, out, DIM_, K, 0, cosb, sinb);
}